// round 14
// baseline (speedup 1.0000x reference)
#include <cuda_runtime.h>
#include <cuda_bf16.h>

// Fixed shapes per reference setup_inputs
#define BB 8
#define CC 3
#define HH 224
#define WW 224
#define NPIX (HH * WW)          // 50176
#define NSEG 196
#define EE 768
#define NROWS (BB * NSEG)       // 1568
#define ACC_STRIDE 64           // 64 floats = 256 B per (rep,row); 6 used
#define NREP 4                  // accumulator replicas

#define SC_BLOCKS 392           // scatter role: (BB*NPIX/4)/256, 4 px/thread
#define PR_BLOCKS 784           // project role: 2 rows per block
#define NBLOCKS (SC_BLOCKS + PR_BLOCKS)   // 1176
#define NTHREADS 256

// Scratch: 4 reps * 1568 rows * 256 B = 1.6 MB. Zero at module load; project
// blocks re-zero every word they consume -> zeroed for the next graph replay.
__device__ float g_acc[(long)NREP * NROWS * ACC_STRIDE];
// Monotone counters, never reset (deterministic per replay):
//   g_ctr  += SC_BLOCKS per launch (scatter arrivals)
//   g_pctr += PR_BLOCKS per launch (project tickets -> launch index)
__device__ unsigned int g_ctr;
__device__ unsigned int g_pctr;

// ---------------------------------------------------------------------------
__device__ __forceinline__ void red_add_v4(float* addr, float a, float b,
                                           float c, float d) {
    asm volatile("red.global.add.v4.f32 [%0], {%1, %2, %3, %4};"
                 :: "l"(addr), "f"(a), "f"(b), "f"(c), "f"(d) : "memory");
}
__device__ __forceinline__ void red_add_v2(float* addr, float a, float b) {
    asm volatile("red.global.add.v2.f32 [%0], {%1, %2};"
                 :: "l"(addr), "f"(a), "f"(b) : "memory");
}
__device__ __forceinline__ float ld_cg(const float* p) {
    float v;
    asm volatile("ld.global.cg.f32 %0, [%1];" : "=f"(v) : "l"(p));
    return v;
}
__device__ __forceinline__ unsigned int ld_acquire_gpu(const unsigned int* p) {
    unsigned int v;
    asm volatile("ld.global.acquire.gpu.u32 %0, [%1];" : "=r"(v) : "l"(p));
    return v;
}

// ---------------------------------------------------------------------------
// One launch, two block roles.
// ---------------------------------------------------------------------------
__global__ void __launch_bounds__(NTHREADS, 6)
fused_roles_kernel(const float* __restrict__ img,
                   const int* __restrict__ seg,
                   const float* __restrict__ Wm,
                   const float* __restrict__ bias,
                   float* __restrict__ out) {
    const int tid = threadIdx.x;

    if (blockIdx.x < SC_BLOCKS) {
        // ================= SCATTER ROLE =================
        int t  = blockIdx.x * NTHREADS + tid;       // one 4-pixel group
        int b  = t / (NPIX / 4);
        int n4 = t - b * (NPIX / 4);
        int n  = n4 * 4;
        int h  = n / WW;
        int w  = n - h * WW;

        const float4 r4 = *reinterpret_cast<const float4*>(img + ((long)(b * CC + 0) * NPIX + n));
        const float4 g4 = *reinterpret_cast<const float4*>(img + ((long)(b * CC + 1) * NPIX + n));
        const float4 b4 = *reinterpret_cast<const float4*>(img + ((long)(b * CC + 2) * NPIX + n));
        const int4   s4 = *reinterpret_cast<const int4*>(seg + (long)b * NPIX + n);

        const float inv = 1.0f / 223.0f;
        float y = (float)h * inv;

        float rr[4] = {r4.x, r4.y, r4.z, r4.w};
        float gg[4] = {g4.x, g4.y, g4.z, g4.w};
        float bb[4] = {b4.x, b4.y, b4.z, b4.w};
        int   ss[4] = {s4.x, s4.y, s4.z, s4.w};

        float* rep = g_acc + (long)(blockIdx.x & (NREP - 1)) * ((long)NROWS * ACC_STRIDE);

#pragma unroll
        for (int i = 0; i < 4; i++) {
            float x = (float)(w + i) * inv;
            float* base = rep + (long)(b * NSEG + ss[i]) * ACC_STRIDE;
            red_add_v4(base, rr[i], gg[i], bb[i], x);
            red_add_v2(base + 4, y, 1.0f);
        }

        // Release: make REDs visible, then arrive. Block exits immediately,
        // freeing its SM slot while the drain completes asynchronously.
        __threadfence();
        __syncthreads();
        if (tid == 0) atomicAdd(&g_ctr, 1u);
        return;
    }

    // ================= PROJECT ROLE =================
    const int pb   = blockIdx.x - SC_BLOCKS;   // 0..783
    const int half = tid >> 7;                 // 0 or 1
    const int t128 = tid & 127;                // thread-in-half
    const int lane = tid & 31;
    const int s    = pb * 2 + half;            // row 0..1567

    // Wait for all scatter arrivals of THIS launch (monotone counters).
    if (tid == 0) {
        unsigned int ticket = atomicAdd(&g_pctr, 1u);
        unsigned int launchi = ticket / (unsigned)PR_BLOCKS;
        unsigned int target  = (launchi + 1u) * (unsigned)SC_BLOCKS;
        while ((int)(ld_acquire_gpu(&g_ctr) - target) < 0) {
            __nanosleep(128);
        }
    }
    __syncthreads();

    // lanes 0-23 of every warp load this row's acc: rep = lane/6, j = lane%6
    float v = 0.0f;
    if (lane < NREP * 6) {
        int rep = lane / 6;
        int j   = lane - rep * 6;
        v = ld_cg(g_acc + (long)rep * ((long)NROWS * ACC_STRIDE)
                        + (long)s * ACC_STRIDE + j);
    }

    float a0 = __shfl_sync(0xffffffffu, v, 0)  + __shfl_sync(0xffffffffu, v, 6)
             + __shfl_sync(0xffffffffu, v, 12) + __shfl_sync(0xffffffffu, v, 18);
    float a1 = __shfl_sync(0xffffffffu, v, 1)  + __shfl_sync(0xffffffffu, v, 7)
             + __shfl_sync(0xffffffffu, v, 13) + __shfl_sync(0xffffffffu, v, 19);
    float a2 = __shfl_sync(0xffffffffu, v, 2)  + __shfl_sync(0xffffffffu, v, 8)
             + __shfl_sync(0xffffffffu, v, 14) + __shfl_sync(0xffffffffu, v, 20);
    float a3 = __shfl_sync(0xffffffffu, v, 3)  + __shfl_sync(0xffffffffu, v, 9)
             + __shfl_sync(0xffffffffu, v, 15) + __shfl_sync(0xffffffffu, v, 21);
    float a4 = __shfl_sync(0xffffffffu, v, 4)  + __shfl_sync(0xffffffffu, v, 10)
             + __shfl_sync(0xffffffffu, v, 16) + __shfl_sync(0xffffffffu, v, 22);
    float cnt = __shfl_sync(0xffffffffu, v, 5)  + __shfl_sync(0xffffffffu, v, 11)
              + __shfl_sync(0xffffffffu, v, 17) + __shfl_sync(0xffffffffu, v, 23);

    bool  empty = !(cnt > 0.0f);
    float invc = empty ? 0.0f : (1.0f / cnt);
    float m0 = a0 * invc;
    float m1 = a1 * invc;
    float m2 = a2 * invc;
    float m3 = a3 * invc;
    float m4 = a4 * invc;

    float* orow = out + (long)s * EE;
#pragma unroll
    for (int k = 0; k < 6; k++) {              // 768 / 128 = 6 cols per thread
        int e = t128 + k * 128;
        float w = m0 * __ldg(Wm + e)
                + m1 * __ldg(Wm + EE + e)
                + m2 * __ldg(Wm + 2 * EE + e)
                + m3 * __ldg(Wm + 3 * EE + e)
                + m4 * __ldg(Wm + 4 * EE + e)
                + __ldg(bias + e);
        orow[e] = empty ? 0.0f : w;
    }

    // Reset the consumed acc words for the next replay (after all warps of
    // this block have read both rows).
    __syncthreads();
    if (tid < 16) {                            // 2 rows * NREP * 2 float4
        int rrow = pb * 2 + (tid >> 3);
        int rep  = (tid >> 1) & 3;
        int h4   = tid & 1;
        reinterpret_cast<float4*>(g_acc + (long)rep * ((long)NROWS * ACC_STRIDE)
                                        + (long)rrow * ACC_STRIDE)[h4] =
            make_float4(0.f, 0.f, 0.f, 0.f);
    }
}

// ---------------------------------------------------------------------------
extern "C" void kernel_launch(void* const* d_in, const int* in_sizes, int n_in,
                              void* d_out, int out_size) {
    const float* img  = (const float*)d_in[0];   // [8,3,224,224]
    const int*   seg  = (const int*)d_in[1];     // [8,224,224]
    const float* Wm   = (const float*)d_in[2];   // [5,768]
    const float* bias = (const float*)d_in[3];   // [768]
    float* out = (float*)d_out;                  // [8,196,768]

    (void)in_sizes; (void)n_in; (void)out_size;

    fused_roles_kernel<<<NBLOCKS, NTHREADS>>>(img, seg, Wm, bias, out);
}

// round 15
// speedup vs baseline: 1.0173x; 1.0173x over previous
#include <cuda_runtime.h>
#include <cuda_bf16.h>

// Fixed shapes per reference setup_inputs
#define BB 8
#define CC 3
#define HH 224
#define WW 224
#define NPIX (HH * WW)          // 50176
#define NSEG 196
#define EE 768
#define NROWS (BB * NSEG)       // 1568
#define ACC_STRIDE 64           // 64 floats = 256 B per (rep,row); 6 used
#define NREP 4                  // accumulator replicas

#define SC_BLOCKS 392           // scatter role: (BB*NPIX/4)/256, 4 px/thread
#define PR_BLOCKS 784           // project role: 2 rows per block
#define NBLOCKS (SC_BLOCKS + PR_BLOCKS)   // 1176 <= 1184 resident (8/SM)
#define NTHREADS 256

#define WSM_FLOATS (5 * EE + EE)          // 4608 floats = 18432 B

// Scratch: 4 reps * 1568 rows * 256 B = 1.6 MB. Zero at module load; project
// blocks re-zero every word they consume -> zeroed for the next graph replay.
__device__ float g_acc[(long)NREP * NROWS * ACC_STRIDE];
// Monotone counters, never reset (deterministic per replay):
//   g_ctr  += SC_BLOCKS per launch (scatter arrivals)
//   g_pctr += PR_BLOCKS per launch (project tickets -> launch index)
__device__ unsigned int g_ctr;
__device__ unsigned int g_pctr;

// ---------------------------------------------------------------------------
__device__ __forceinline__ void red_add_v4(float* addr, float a, float b,
                                           float c, float d) {
    asm volatile("red.global.add.v4.f32 [%0], {%1, %2, %3, %4};"
                 :: "l"(addr), "f"(a), "f"(b), "f"(c), "f"(d) : "memory");
}
__device__ __forceinline__ void red_add_v2(float* addr, float a, float b) {
    asm volatile("red.global.add.v2.f32 [%0], {%1, %2};"
                 :: "l"(addr), "f"(a), "f"(b) : "memory");
}
__device__ __forceinline__ float ld_cg(const float* p) {
    float v;
    asm volatile("ld.global.cg.f32 %0, [%1];" : "=f"(v) : "l"(p));
    return v;
}
__device__ __forceinline__ unsigned int ld_acquire_gpu(const unsigned int* p) {
    unsigned int v;
    asm volatile("ld.global.acquire.gpu.u32 %0, [%1];" : "=r"(v) : "l"(p));
    return v;
}

// ---------------------------------------------------------------------------
// One launch, two block roles, single co-resident wave.
// ---------------------------------------------------------------------------
__global__ void __launch_bounds__(NTHREADS, 8)
fused_roles_kernel(const float* __restrict__ img,
                   const int* __restrict__ seg,
                   const float* __restrict__ Wm,
                   const float* __restrict__ bias,
                   float* __restrict__ out) {
    __shared__ float wsm[WSM_FLOATS];      // W (5x768) then bias (768)
    const int tid = threadIdx.x;

    if (blockIdx.x < SC_BLOCKS) {
        // ================= SCATTER ROLE (proven shape) =================
        int t  = blockIdx.x * NTHREADS + tid;       // one 4-pixel group
        int b  = t / (NPIX / 4);
        int n4 = t - b * (NPIX / 4);
        int n  = n4 * 4;
        int h  = n / WW;
        int w  = n - h * WW;

        const float4 r4 = *reinterpret_cast<const float4*>(img + ((long)(b * CC + 0) * NPIX + n));
        const float4 g4 = *reinterpret_cast<const float4*>(img + ((long)(b * CC + 1) * NPIX + n));
        const float4 b4 = *reinterpret_cast<const float4*>(img + ((long)(b * CC + 2) * NPIX + n));
        const int4   s4 = *reinterpret_cast<const int4*>(seg + (long)b * NPIX + n);

        const float inv = 1.0f / 223.0f;
        float y = (float)h * inv;

        float rr[4] = {r4.x, r4.y, r4.z, r4.w};
        float gg[4] = {g4.x, g4.y, g4.z, g4.w};
        float bb[4] = {b4.x, b4.y, b4.z, b4.w};
        int   ss[4] = {s4.x, s4.y, s4.z, s4.w};

        float* rep = g_acc + (long)(blockIdx.x & (NREP - 1)) * ((long)NROWS * ACC_STRIDE);

#pragma unroll
        for (int i = 0; i < 4; i++) {
            float x = (float)(w + i) * inv;
            float* base = rep + (long)(b * NSEG + ss[i]) * ACC_STRIDE;
            red_add_v4(base, rr[i], gg[i], bb[i], x);
            red_add_v2(base + 4, y, 1.0f);
        }

        // Release: make REDs visible, arrive, exit (frees the SM slot).
        __threadfence();
        __syncthreads();
        if (tid == 0) atomicAdd(&g_ctr, 1u);
        return;
    }

    // ================= PROJECT ROLE =================
    const int pb   = blockIdx.x - SC_BLOCKS;   // 0..783
    const int half = tid >> 7;                 // 0 or 1
    const int t128 = tid & 127;                // thread-in-half
    const int lane = tid & 31;
    const int s    = pb * 2 + half;            // row 0..1567

    // ---- Prefetch W + bias into smem WHILE scatter runs ----
    {
        float4* dst = reinterpret_cast<float4*>(wsm);
        const float4* srcW = reinterpret_cast<const float4*>(Wm);
        const float4* srcB = reinterpret_cast<const float4*>(bias);
#pragma unroll
        for (int k = 0; k < 5; k++) {          // 1152 float4 over 256 threads
            int i = tid + k * NTHREADS;
            if (i < 1152) dst[i] = (i < 960) ? srcW[i] : srcB[i - 960];
        }
    }

    // ---- Wait for all scatter arrivals of THIS launch ----
    if (tid == 0) {
        unsigned int ticket  = atomicAdd(&g_pctr, 1u);
        unsigned int launchi = ticket / (unsigned)PR_BLOCKS;
        unsigned int target  = (launchi + 1u) * (unsigned)SC_BLOCKS;
        while ((int)(ld_acquire_gpu(&g_ctr) - target) < 0) {
            __nanosleep(64);
        }
    }
    __syncthreads();   // also publishes wsm to all threads

    // ---- Acc read: lanes 0-23 of every warp, shfl-reduce over replicas ----
    float v = 0.0f;
    if (lane < NREP * 6) {
        int rep = lane / 6;
        int j   = lane - rep * 6;
        v = ld_cg(g_acc + (long)rep * ((long)NROWS * ACC_STRIDE)
                        + (long)s * ACC_STRIDE + j);
    }

    float a0 = __shfl_sync(0xffffffffu, v, 0)  + __shfl_sync(0xffffffffu, v, 6)
             + __shfl_sync(0xffffffffu, v, 12) + __shfl_sync(0xffffffffu, v, 18);
    float a1 = __shfl_sync(0xffffffffu, v, 1)  + __shfl_sync(0xffffffffu, v, 7)
             + __shfl_sync(0xffffffffu, v, 13) + __shfl_sync(0xffffffffu, v, 19);
    float a2 = __shfl_sync(0xffffffffu, v, 2)  + __shfl_sync(0xffffffffu, v, 8)
             + __shfl_sync(0xffffffffu, v, 14) + __shfl_sync(0xffffffffu, v, 20);
    float a3 = __shfl_sync(0xffffffffu, v, 3)  + __shfl_sync(0xffffffffu, v, 9)
             + __shfl_sync(0xffffffffu, v, 15) + __shfl_sync(0xffffffffu, v, 21);
    float a4 = __shfl_sync(0xffffffffu, v, 4)  + __shfl_sync(0xffffffffu, v, 10)
             + __shfl_sync(0xffffffffu, v, 16) + __shfl_sync(0xffffffffu, v, 22);
    float cnt = __shfl_sync(0xffffffffu, v, 5)  + __shfl_sync(0xffffffffu, v, 11)
              + __shfl_sync(0xffffffffu, v, 17) + __shfl_sync(0xffffffffu, v, 23);

    bool  empty = !(cnt > 0.0f);
    float invc = empty ? 0.0f : (1.0f / cnt);
    float m0 = a0 * invc;
    float m1 = a1 * invc;
    float m2 = a2 * invc;
    float m3 = a3 * invc;
    float m4 = a4 * invc;

    // ---- FMA fan-out from smem W (conflict-free stride-1 LDS) ----
    float* orow = out + (long)s * EE;
#pragma unroll
    for (int k = 0; k < 6; k++) {              // 768 / 128 = 6 cols per thread
        int e = t128 + k * 128;
        float w = m0 * wsm[e]
                + m1 * wsm[EE + e]
                + m2 * wsm[2 * EE + e]
                + m3 * wsm[3 * EE + e]
                + m4 * wsm[4 * EE + e]
                + wsm[5 * EE + e];
        orow[e] = empty ? 0.0f : w;
    }

    // ---- Reset consumed acc words for the next replay ----
    __syncthreads();
    if (tid < 16) {                            // 2 rows * NREP * 2 float4
        int rrow = pb * 2 + (tid >> 3);
        int rep  = (tid >> 1) & 3;
        int h4   = tid & 1;
        reinterpret_cast<float4*>(g_acc + (long)rep * ((long)NROWS * ACC_STRIDE)
                                        + (long)rrow * ACC_STRIDE)[h4] =
            make_float4(0.f, 0.f, 0.f, 0.f);
    }
}

// ---------------------------------------------------------------------------
extern "C" void kernel_launch(void* const* d_in, const int* in_sizes, int n_in,
                              void* d_out, int out_size) {
    const float* img  = (const float*)d_in[0];   // [8,3,224,224]
    const int*   seg  = (const int*)d_in[1];     // [8,224,224]
    const float* Wm   = (const float*)d_in[2];   // [5,768]
    const float* bias = (const float*)d_in[3];   // [768]
    float* out = (float*)d_out;                  // [8,196,768]

    (void)in_sizes; (void)n_in; (void)out_size;

    fused_roles_kernel<<<NBLOCKS, NTHREADS>>>(img, seg, Wm, bias, out);
}